// round 17
// baseline (speedup 1.0000x reference)
#include <cuda_runtime.h>
#include <math.h>
#include <stdint.h>

#define Bx 4
#define Sx 128
#define Dx 256
#define Hx 8

static __device__ float g_Vp [4][Bx*Sx*Dx];   // V partials (K quarters), no bias
static __device__ float g_QKp[4][Bx*Sx*64];   // QK partials, no bias
static __device__ float g_AO [Bx*Sx*Dx];      // attention output (pre-Wo)

// ---------------------------------------------------------------------------
// Quarter-K GEMM (R14-proven, k1 = 9.7us @ occ 39%):
// C = sum_{k in 64-chunk kc} A[m][k]*B[n][k]  (NT). 32m x 32n, 256 thr.
// Warp w: n-group ng=w&3, k4-parity kp=w>>2. As/Bs [32][17] float4.
// qk mode gathers B rows from Wq|Wk: col -> h=col>>3, side=(col>>2)&1,
// w=col&3, row = h*32+w.
// ---------------------------------------------------------------------------
__device__ __forceinline__ void gemm_q(
    const float4* __restrict__ A4,
    const float4* __restrict__ Bq4, const float4* __restrict__ Bk4,
    float* __restrict__ C, int m0, int n0, int cstride, int qk, int kc,
    float* sm)
{
    float4* As = (float4*)sm;            // [32][17] f4
    float4* Bs = (float4*)sm + 544;      // [32][17] f4
    const int tid  = threadIdx.x;
    const int lane = tid & 31;
    const int w    = tid >> 5;
    const int ng   = w & 3;
    const int kp   = w >> 2;

    float acc[8][2];
#pragma unroll
    for (int j = 0; j < 8; j++) { acc[j][0] = 0.f; acc[j][1] = 0.f; }

    const float4* Ap = As + lane*17 + kp;
    const float4* Bp = Bs + (ng*8)*17 + kp;

#pragma unroll
    for (int t = 0; t < 2; t++) {
        const int idx = tid + (t << 8);
        const int r = idx >> 4, c = idx & 15;
        As[r*17 + c] = A4[(m0 + r)*64 + (kc << 4) + c];
        int brow;
        const float4* bp;
        if (qk) {
            const int col = n0 + r;
            brow = ((col >> 3)*32) + (col & 3);
            bp = ((col >> 2) & 1) ? Bk4 : Bq4;
        } else {
            brow = n0 + r;
            bp = Bq4;
        }
        Bs[r*17 + c] = bp[brow*64 + (kc << 4) + c];
    }
    __syncthreads();

#pragma unroll
    for (int k4 = 0; k4 < 8; k4++) {
        const float4 a = Ap[k4*2];
#pragma unroll
        for (int j = 0; j < 8; j++) {
            const float4 b = Bp[j*17 + k4*2];
            acc[j][0] = fmaf(a.x, b.x, acc[j][0]);
            acc[j][1] = fmaf(a.y, b.y, acc[j][1]);
            acc[j][0] = fmaf(a.z, b.z, acc[j][0]);
            acc[j][1] = fmaf(a.w, b.w, acc[j][1]);
        }
    }
    __syncthreads();

    float* red = sm;
    if (kp == 1) {
#pragma unroll
        for (int j = 0; j < 8; j++) {
            red[(ng*32 + lane)*17 + j*2    ] = acc[j][0];
            red[(ng*32 + lane)*17 + j*2 + 1] = acc[j][1];
        }
    }
    __syncthreads();
    if (kp == 0) {
        const float* rp = &red[(ng*32 + lane)*17];
        float o[8];
#pragma unroll
        for (int j = 0; j < 8; j++)
            o[j] = acc[j][0] + acc[j][1] + rp[j*2] + rp[j*2 + 1];
        float* cp = &C[(m0 + lane)*cstride + n0 + ng*8];
        *(float4*)cp       = make_float4(o[0], o[1], o[2], o[3]);
        *(float4*)(cp + 4) = make_float4(o[4], o[5], o[6], o[7]);
    }
}

// ---------------------------------------------------------------------------
// Kernel 1 (R14-proven): 640 blocks (~4.3/SM):
//   [0,512)   V-GEMM:  128 tiles x 4 K-quarters
//   [512,640) QK-GEMM:  32 tiles x 4 K-quarters
// ---------------------------------------------------------------------------
__global__ void __launch_bounds__(256, 4) k1_gemms(
    const float* __restrict__ x,
    const float* __restrict__ Wq, const float* __restrict__ Wk,
    const float* __restrict__ Wv)
{
    __shared__ float sm[4352];   // 17.4KB
    const int bx = blockIdx.x;
    if (bx < 512) {
        const int tile = bx >> 2, kc = bx & 3;
        gemm_q((const float4*)x, (const float4*)Wv, nullptr,
               g_Vp[kc], (tile >> 3) << 5, (tile & 7) << 5, 256, 0, kc, sm);
    } else {
        const int q = bx - 512;
        const int tile = q >> 2, kc = q & 3;
        gemm_q((const float4*)x, (const float4*)Wq, (const float4*)Wk,
               g_QKp[kc], (tile >> 1) << 5, (tile & 1) << 5, 64, 1, kc, sm);
    }
}

// ---------------------------------------------------------------------------
// Kernel 2: attention, 256 blocks = (bh, 16-row i-group), 256 threads.
// Phase-2 j-loop split in half across thread pairs; writeback decodes
// (il = tid>>3, p = tid&7) to MATCH the Part storage packing ((il<<3)+p).
// score(i,j) = prod_{w=1..3}( cos(th_w)cos(q_iw) - sin(th_w)sin(q_iw)cos(k_jw) )
// Scores bounded (|s| <= 0.177) -> single-pass softmax.
// ---------------------------------------------------------------------------
__global__ void __launch_bounds__(256) attn_kernel(
    const float* __restrict__ ap,
    const float* __restrict__ bq, const float* __restrict__ bk,
    const float* __restrict__ bv)
{
    const int bx = blockIdx.x;
    const int ig = bx & 7;           // 8 groups of 16 i-rows
    const int bh = bx >> 3;
    const int b = bh >> 3, h = bh & 7;

    __shared__ float4 Vs[1024];      // [j][p]            16KB
    __shared__ float4 CKs[128];      //                    2KB
    __shared__ float  AB[16*6];
    __shared__ float  E[128*17];     // [j][il], pad 17   8.5KB
    __shared__ float  Psum[16*17];   // [il][jg]
    __shared__ float  Sinv[16];
    __shared__ float4 Part[256];     // [(il<<3)+p][half]  4KB

    const int tid = threadIdx.x;
    const float4* V0 = (const float4*)g_Vp[0];
    const float4* V1 = (const float4*)g_Vp[1];
    const float4* V2 = (const float4*)g_Vp[2];
    const float4* V3 = (const float4*)g_Vp[3];
#pragma unroll
    for (int t = 0; t < 4; t++) {
        const int idx = tid + (t << 8);
        const int j = idx >> 3, p = idx & 7;
        const int gi = (b*Sx + j)*64 + h*8 + p;
        const float4 a0 = V0[gi];
        const float4 a1 = V1[gi];
        const float4 a2 = V2[gi];
        const float4 a3 = V3[gi];
        const float4 bb = *(const float4*)&bv[h*32 + p*4];
        Vs[idx] = make_float4(a0.x + a1.x + a2.x + a3.x + bb.x,
                              a0.y + a1.y + a2.y + a3.y + bb.y,
                              a0.z + a1.z + a2.z + a3.z + bb.z,
                              a0.w + a1.w + a2.w + a3.w + bb.w);
    }

    const float PI = 3.14159265358979323846f;
    if (tid < 128) {
        // k-side trig for row j
        const int j = tid;
        const int base = (b*Sx + j)*64 + h*8 + 4;
        float v[4];
#pragma unroll
        for (int q = 0; q < 4; q++)
            v[q] = g_QKp[0][base + q] + g_QKp[1][base + q]
                 + g_QKp[2][base + q] + g_QKp[3][base + q] + bk[h*32 + q];
        const float mn = fminf(fminf(v[0], v[1]), fminf(v[2], v[3]));
        const float mx = fmaxf(fmaxf(v[0], v[1]), fmaxf(v[2], v[3]));
        const float sc = PI / (mx - mn + 1e-8f);
        CKs[j] = make_float4(cosf((v[1] - mn)*sc), cosf((v[2] - mn)*sc),
                             cosf((v[3] - mn)*sc), 0.f);
    } else if (tid < 144) {
        // q-side trig for row i (16 rows)
        const int il = tid - 128;
        const int i  = (ig << 4) + il;
        const int base = (b*Sx + i)*64 + h*8;
        float v[4];
#pragma unroll
        for (int q = 0; q < 4; q++)
            v[q] = g_QKp[0][base + q] + g_QKp[1][base + q]
                 + g_QKp[2][base + q] + g_QKp[3][base + q] + bq[h*32 + q];
        const float mn = fminf(fminf(v[0], v[1]), fminf(v[2], v[3]));
        const float mx = fmaxf(fmaxf(v[0], v[1]), fmaxf(v[2], v[3]));
        const float sc = PI / (mx - mn + 1e-8f);
#pragma unroll
        for (int w = 0; w < 3; w++) {
            float sn, cs;
            sincosf((v[w + 1] - mn)*sc, &sn, &cs);
            const float th = ap[w + 1];
            AB[il*6 + w*2 + 0] = cosf(th) * cs;
            AB[il*6 + w*2 + 1] = sinf(th) * sn;
        }
    }
    __syncthreads();

    // phase 1: exp scores. il = tid&15; jg = tid>>4 handles 8 j's.
    {
        const int il = tid & 15;
        const int jg = tid >> 4;
        const float A1 = AB[il*6+0], B1 = AB[il*6+1];
        const float A2 = AB[il*6+2], B2 = AB[il*6+3];
        const float A3 = AB[il*6+4], B3 = AB[il*6+5];
        const float SCALE = 0.17677669529663687f;   // 1/sqrt(32)
        float s = 0.f;
#pragma unroll
        for (int jj = 0; jj < 8; jj++) {
            const int j = (jg << 3) + jj;
            const float4 ck = CKs[j];
            const float sc = (A1 - B1*ck.x) * (A2 - B2*ck.y) * (A3 - B3*ck.z);
            const float e = __expf(sc * SCALE);
            E[j*17 + il] = e;
            s += e;
        }
        Psum[il*17 + jg] = s;
    }
    __syncthreads();
    if (tid < 16) {
        float s = 0.f;
#pragma unroll
        for (int jg = 0; jg < 16; jg++) s += Psum[tid*17 + jg];
        Sinv[tid] = 1.0f / s;
    }
    __syncthreads();

    // phase 2: thread = (il = tid&15, p = (tid>>4)&7, half = tid>>7); 64 j's.
    {
        const int il   = tid & 15;
        const int p    = (tid >> 4) & 7;
        const int half = tid >> 7;
        const int j0   = half << 6;
        float4 o = make_float4(0.f, 0.f, 0.f, 0.f);
#pragma unroll 8
        for (int jj = 0; jj < 64; jj++) {
            const int j = j0 + jj;
            const float e = E[j*17 + il];
            const float4 v = Vs[(j << 3) + p];
            o.x = fmaf(e, v.x, o.x);
            o.y = fmaf(e, v.y, o.y);
            o.z = fmaf(e, v.z, o.z);
            o.w = fmaf(e, v.w, o.w);
        }
        Part[((il << 3) + p)*2 + half] = o;
    }
    __syncthreads();

    // writeback: decode MATCHES storage packing: il = tid>>3, p = tid&7.
    if (tid < 128) {
        const int il = tid >> 3;
        const int p  = tid & 7;
        const float4 o0 = Part[tid*2];
        const float4 o1 = Part[tid*2 + 1];
        const float inv = Sinv[il];
        const int i = (ig << 4) + il;
        ((float4*)g_AO)[(b*Sx + i)*64 + h*8 + p] =
            make_float4((o0.x + o1.x)*inv, (o0.y + o1.y)*inv,
                        (o0.z + o1.z)*inv, (o0.w + o1.w)*inv);
    }
}

// ---------------------------------------------------------------------------
// Kernel 3 (R9-proven): out = g_AO @ Wo.T + bo. Full K=256, 128 blocks,
// double-buffered K-chunks, plain STG epilogue with bias.
// ---------------------------------------------------------------------------
__global__ void __launch_bounds__(256) k3_ogemm(
    const float* __restrict__ Wo, const float* __restrict__ bo,
    float* __restrict__ out)
{
    __shared__ float sm[8448];
    float4* As = (float4*)sm;
    float4* Bs = (float4*)sm + 32*33;

    const int tile = blockIdx.x;
    const int m0 = (tile >> 3) << 5;
    const int n0 = (tile & 7) << 5;
    const int tid  = threadIdx.x;
    const int lane = tid & 31;
    const int w    = tid >> 5;
    const int ng   = w & 3;
    const int kp   = w >> 2;

    const float4* A4 = (const float4*)g_AO;
    const float4* B4 = (const float4*)Wo;

    float acc[8][2];
#pragma unroll
    for (int j = 0; j < 8; j++) { acc[j][0] = 0.f; acc[j][1] = 0.f; }

    const float4* Ap = As + lane*33 + kp;
    const float4* Bp = Bs + (ng*8)*33 + kp;

    int srow[4], scol[4];
#pragma unroll
    for (int t = 0; t < 4; t++) {
        const int idx = tid + (t << 8);
        srow[t] = idx >> 5;
        scol[t] = idx & 31;
    }

    float4 ra[4], rb[4];
#pragma unroll
    for (int t = 0; t < 4; t++) {
        ra[t] = A4[(m0 + srow[t])*64 + scol[t]];
        rb[t] = B4[(n0 + srow[t])*64 + scol[t]];
    }
#pragma unroll
    for (int t = 0; t < 4; t++) {
        As[srow[t]*33 + scol[t]] = ra[t];
        Bs[srow[t]*33 + scol[t]] = rb[t];
    }
    __syncthreads();

#pragma unroll
    for (int t = 0; t < 4; t++) {
        ra[t] = A4[(m0 + srow[t])*64 + 32 + scol[t]];
        rb[t] = B4[(n0 + srow[t])*64 + 32 + scol[t]];
    }

#pragma unroll 4
    for (int k4 = 0; k4 < 16; k4++) {
        const float4 a = Ap[k4*2];
#pragma unroll
        for (int j = 0; j < 8; j++) {
            const float4 b = Bp[j*33 + k4*2];
            acc[j][0] = fmaf(a.x, b.x, acc[j][0]);
            acc[j][1] = fmaf(a.y, b.y, acc[j][1]);
            acc[j][0] = fmaf(a.z, b.z, acc[j][0]);
            acc[j][1] = fmaf(a.w, b.w, acc[j][1]);
        }
    }
    __syncthreads();
#pragma unroll
    for (int t = 0; t < 4; t++) {
        As[srow[t]*33 + scol[t]] = ra[t];
        Bs[srow[t]*33 + scol[t]] = rb[t];
    }
    __syncthreads();
#pragma unroll 4
    for (int k4 = 0; k4 < 16; k4++) {
        const float4 a = Ap[k4*2];
#pragma unroll
        for (int j = 0; j < 8; j++) {
            const float4 b = Bp[j*33 + k4*2];
            acc[j][0] = fmaf(a.x, b.x, acc[j][0]);
            acc[j][1] = fmaf(a.y, b.y, acc[j][1]);
            acc[j][0] = fmaf(a.z, b.z, acc[j][0]);
            acc[j][1] = fmaf(a.w, b.w, acc[j][1]);
        }
    }
    __syncthreads();

    float* red = sm;
    if (kp == 1) {
#pragma unroll
        for (int j = 0; j < 8; j++) {
            red[(ng*32 + lane)*17 + j*2    ] = acc[j][0];
            red[(ng*32 + lane)*17 + j*2 + 1] = acc[j][1];
        }
    }
    __syncthreads();
    if (kp == 0) {
        const int n = n0 + ng*8;
        const float* rp = &red[(ng*32 + lane)*17];
        float o[8];
#pragma unroll
        for (int j = 0; j < 8; j++)
            o[j] = acc[j][0] + acc[j][1] + rp[j*2] + rp[j*2 + 1] + bo[n + j];
        float* cp = &out[(m0 + lane)*256 + n];
        *(float4*)cp       = make_float4(o[0], o[1], o[2], o[3]);
        *(float4*)(cp + 4) = make_float4(o[4], o[5], o[6], o[7]);
    }
}

// ---------------------------------------------------------------------------
extern "C" void kernel_launch(void* const* d_in, const int* in_sizes, int n_in,
                              void* d_out, int out_size)
{
    const float* x  = (const float*)d_in[0];
    const float* Wq = (const float*)d_in[1];
    const float* bq = (const float*)d_in[2];
    const float* Wk = (const float*)d_in[3];
    const float* bk = (const float*)d_in[4];
    const float* Wv = (const float*)d_in[5];
    const float* bv = (const float*)d_in[6];
    const float* Wo = (const float*)d_in[7];
    const float* bo = (const float*)d_in[8];
    const float* ap = (const float*)d_in[9];
    float* out = (float*)d_out;

    k1_gemms<<<640, 256>>>(x, Wq, Wk, Wv);
    attn_kernel<<<256, 256>>>(ap, bq, bk, bv);
    k3_ogemm<<<128, 256>>>(Wo, bo, out);
}